// round 2
// baseline (speedup 1.0000x reference)
#include <cuda_runtime.h>
#include <math.h>

#define NTOK 2048      // total tokens (B=4, L=512)
#define DMODEL 128
#define DINNER 256
#define NSTATE 64
#define NRANK 8
#define NHID 256
#define DBLW 136       // R + 2S

// ---------------- scratch (device globals; no allocation allowed) ----------------
__device__ float g_xn   [NTOK*DMODEL];
__device__ float g_xz   [NTOK*2*DINNER];
__device__ float g_xh   [NTOK*DINNER];
__device__ float g_dbl  [NTOK*DBLW];
__device__ float g_dt   [NTOK*DINNER];
__device__ float g_y    [NTOK*DINNER];
__device__ float g_y2   [NTOK*DINNER];
__device__ float g_xoacc[NTOK*DMODEL];
__device__ float g_xo   [NTOK*DMODEL];
__device__ float g_xn2  [NTOK*DMODEL];
__device__ float g_g1   [NTOK*NHID];
__device__ float g_h2   [NTOK*NHID];
__device__ float g_g2   [NTOK*DMODEL];
__device__ float g_acoef[DINNER*NSTATE];
__device__ float g_mu1[NHID],  g_rstd1[NHID];
__device__ float g_mu2[DMODEL], g_rstd2[DMODEL];

__device__ __forceinline__ float fast_ex2(float x) {
    float y; asm("ex2.approx.f32 %0, %1;" : "=f"(y) : "f"(x)); return y;
}
__device__ __forceinline__ float fast_sigmoid(float x) {
    return 1.f / (1.f + __expf(-x));
}

// ---------------- layernorm over D=128, one block per token ----------------
__global__ void ln128(const float* __restrict__ x, const float* __restrict__ w,
                      const float* __restrict__ b, float* __restrict__ o) {
    int t = blockIdx.x, c = threadIdx.x;
    float v = x[t*128 + c];
    float s = v, s2 = v*v;
    #pragma unroll
    for (int off = 16; off; off >>= 1) {
        s  += __shfl_xor_sync(0xffffffffu, s,  off);
        s2 += __shfl_xor_sync(0xffffffffu, s2, off);
    }
    __shared__ float rs[4], rs2[4];
    int wid = c >> 5, ln = c & 31;
    if (!ln) { rs[wid] = s; rs2[wid] = s2; }
    __syncthreads();
    s  = rs[0]+rs[1]+rs[2]+rs[3];
    s2 = rs2[0]+rs2[1]+rs2[2]+rs2[3];
    float mu  = s * 0.0078125f;
    float var = s2 * 0.0078125f - mu*mu;
    float rstd = rsqrtf(var + 1e-5f);
    o[t*128 + c] = (v - mu) * rstd * w[c] + b[c];
}

// ---------------- fused: xo = x + LN(x_o)*n1 ; xn2 = LN(xo)*n2 ----------------
__global__ void norm12(const float* __restrict__ x,
                       const float* __restrict__ n1w, const float* __restrict__ n1b,
                       const float* __restrict__ n2w, const float* __restrict__ n2b) {
    int t = blockIdx.x, c = threadIdx.x;
    __shared__ float rs[4], rs2[4];
    int wid = c >> 5, ln = c & 31;

    float v = g_xoacc[t*128 + c];
    float s = v, s2 = v*v;
    #pragma unroll
    for (int off = 16; off; off >>= 1) {
        s  += __shfl_xor_sync(0xffffffffu, s,  off);
        s2 += __shfl_xor_sync(0xffffffffu, s2, off);
    }
    if (!ln) { rs[wid] = s; rs2[wid] = s2; }
    __syncthreads();
    s  = rs[0]+rs[1]+rs[2]+rs[3];
    s2 = rs2[0]+rs2[1]+rs2[2]+rs2[3];
    float mu  = s * 0.0078125f;
    float var = s2 * 0.0078125f - mu*mu;
    float xoc = x[t*128 + c] + (v - mu) * rsqrtf(var + 1e-5f) * n1w[c] + n1b[c];
    g_xo[t*128 + c] = xoc;
    __syncthreads();

    s = xoc; s2 = xoc*xoc;
    #pragma unroll
    for (int off = 16; off; off >>= 1) {
        s  += __shfl_xor_sync(0xffffffffu, s,  off);
        s2 += __shfl_xor_sync(0xffffffffu, s2, off);
    }
    if (!ln) { rs[wid] = s; rs2[wid] = s2; }
    __syncthreads();
    s  = rs[0]+rs[1]+rs[2]+rs[3];
    s2 = rs2[0]+rs2[1]+rs2[2]+rs2[3];
    mu  = s * 0.0078125f;
    var = s2 * 0.0078125f - mu*mu;
    g_xn2[t*128 + c] = (xoc - mu) * rsqrtf(var + 1e-5f) * n2w[c] + n2b[c];
}

// ---------------- generic tiled GEMM: C[M,N] = A[M,K] * B ----------------
// BKN=true : B stored (K,N) row-major.  BKN=false : B stored (N,K) row-major.
template<bool BKN, bool ACC>
__global__ void gemm64(const float* __restrict__ A, const float* __restrict__ B,
                       float* __restrict__ C, int M, int N, int K) {
    __shared__ float As[16][64];
    __shared__ float Bs[16][68];
    int tid = threadIdx.x;
    int tx = tid & 15, ty = tid >> 4;
    int row0 = blockIdx.y * 64, col0 = blockIdx.x * 64;
    float acc[4][4] = {};
    for (int k0 = 0; k0 < K; k0 += 16) {
        #pragma unroll
        for (int i = tid; i < 64*16; i += 256) {
            int m = i >> 4, kk = i & 15;
            As[kk][m] = A[(row0+m)*K + k0 + kk];
        }
        #pragma unroll
        for (int i = tid; i < 16*64; i += 256) {
            int kk = i >> 6, n = i & 63;
            int gn = col0 + n;
            float v = 0.f;
            if (gn < N) v = BKN ? B[(k0+kk)*N + gn] : B[gn*K + k0 + kk];
            Bs[kk][n] = v;
        }
        __syncthreads();
        #pragma unroll
        for (int kk = 0; kk < 16; kk++) {
            float a[4], bb[4];
            #pragma unroll
            for (int i = 0; i < 4; i++) a[i]  = As[kk][ty*4+i];
            #pragma unroll
            for (int j = 0; j < 4; j++) bb[j] = Bs[kk][tx*4+j];
            #pragma unroll
            for (int i = 0; i < 4; i++)
                #pragma unroll
                for (int j = 0; j < 4; j++)
                    acc[i][j] = fmaf(a[i], bb[j], acc[i][j]);
        }
        __syncthreads();
    }
    #pragma unroll
    for (int i = 0; i < 4; i++) {
        int r = row0 + ty*4 + i;
        #pragma unroll
        for (int j = 0; j < 4; j++) {
            int cc = col0 + tx*4 + j;
            if (cc < N) {
                if (ACC) C[r*N + cc] += acc[i][j];
                else     C[r*N + cc]  = acc[i][j];
            }
        }
    }
}

// ---------------- A coefficient: -exp(A_log) * log2(e) ----------------
__global__ void acoef_kernel(const float* __restrict__ A_log) {
    int idx = blockIdx.x*256 + threadIdx.x;
    if (idx < DINNER*NSTATE)
        g_acoef[idx] = -expf(A_log[idx]) * 1.4426950408889634f;
}

// ---------------- causal depthwise conv (K=4) + SiLU ----------------
__global__ void conv_silu(const float* __restrict__ cw, const float* __restrict__ cb, int lr) {
    int t = blockIdx.x, d = threadIdx.x;          // 2048 blocks x 256 threads
    int pos = t & (lr - 1);
    float acc = cb[d];
    #pragma unroll
    for (int j = 0; j < 4; j++) {
        int pp = pos - 3 + j;
        if (pp >= 0) acc = fmaf(g_xz[(t-3+j)*512 + d], cw[d*4 + j], acc);
    }
    g_xh[t*256 + d] = acc * fast_sigmoid(acc);
}

// ---------------- dt = softplus(dbl[:, :8] @ dtW + dtb) ----------------
__global__ void dt_kernel(const float* __restrict__ dtW, const float* __restrict__ dtb) {
    int t = blockIdx.x, d = threadIdx.x;
    float acc = dtb[d];
    #pragma unroll
    for (int r = 0; r < 8; r++)
        acc = fmaf(g_dbl[t*DBLW + r], dtW[r*256 + d], acc);
    g_dt[t*256 + d] = (acc > 15.f) ? acc : log1pf(__expf(acc));
}

// ---------------- copy Cm slice to output ----------------
__global__ void cm_copy(float* __restrict__ dst) {
    int idx = blockIdx.x*256 + threadIdx.x;       // 2048*64
    dst[idx] = g_dbl[(idx >> 6)*DBLW + 72 + (idx & 63)];
}

// ---------------- selective scan: warp per (chunk, d), 2 states/thread ----------------
__global__ void scan_kernel(int lr) {
    int chunk = blockIdx.x;
    int w = threadIdx.x >> 5, lane = threadIdx.x & 31;
    int d = blockIdx.y*8 + w;
    int t0 = chunk * lr;
    float ac0 = g_acoef[d*64 + lane];
    float ac1 = g_acoef[d*64 + lane + 32];
    float h0 = 0.f, h1 = 0.f;
    __shared__ float sB[16][64], sC[16][64];
    __shared__ float sdt[16][8], sxh[16][8];
    for (int tb = 0; tb < lr; tb += 16) {
        __syncthreads();
        for (int i = threadIdx.x; i < 1024; i += 256) {
            int ii = i >> 6, ss = i & 63;
            const float* base = g_dbl + (t0+tb+ii)*DBLW;
            sB[ii][ss] = base[8 + ss];
            sC[ii][ss] = base[72 + ss];
        }
        if (lane < 16) sdt[lane][w]      = g_dt[(t0+tb+lane)*256 + d];
        else           sxh[lane-16][w]   = g_xh[(t0+tb+lane-16)*256 + d];
        __syncthreads();
        #pragma unroll
        for (int i = 0; i < 16; i++) {
            float dtv = sdt[i][w];
            float bx  = dtv * sxh[i][w];
            float a0  = fast_ex2(dtv * ac0);
            float a1  = fast_ex2(dtv * ac1);
            h0 = fmaf(a0, h0, bx * sB[i][lane]);
            h1 = fmaf(a1, h1, bx * sB[i][lane+32]);
            float p = h0 * sC[i][lane] + h1 * sC[i][lane+32];
            #pragma unroll
            for (int o = 16; o; o >>= 1) p += __shfl_xor_sync(0xffffffffu, p, o);
            if (lane == 0) g_y[(t0+tb+i)*256 + d] = p;
        }
    }
}

// ---------------- y2 = (y + D*xh) * silu(z) ----------------
__global__ void y2_kernel(const float* __restrict__ Dp) {
    int t = blockIdx.x, d = threadIdx.x;
    int idx = t*256 + d;
    float zv = g_xz[t*512 + 256 + d];
    g_y2[idx] = (g_y[idx] + Dp[d]*g_xh[idx]) * (zv * fast_sigmoid(zv));
}

// ---------------- batchnorm stats over 2048 tokens per channel ----------------
__global__ void bn_stats(const float* __restrict__ g, int C,
                         float* __restrict__ mu, float* __restrict__ rstd) {
    int ch = blockIdx.x;
    float s = 0.f, s2 = 0.f;
    for (int t = threadIdx.x; t < NTOK; t += 256) {
        float v = g[t*C + ch];
        s += v; s2 += v*v;
    }
    #pragma unroll
    for (int off = 16; off; off >>= 1) {
        s  += __shfl_xor_sync(0xffffffffu, s,  off);
        s2 += __shfl_xor_sync(0xffffffffu, s2, off);
    }
    __shared__ float rs[8], rs2[8];
    int wid = threadIdx.x >> 5, ln = threadIdx.x & 31;
    if (!ln) { rs[wid] = s; rs2[wid] = s2; }
    __syncthreads();
    if (threadIdx.x == 0) {
        float S = 0.f, S2 = 0.f;
        #pragma unroll
        for (int k = 0; k < 8; k++) { S += rs[k]; S2 += rs2[k]; }
        float m = S * (1.f/2048.f);
        float var = S2 * (1.f/2048.f) - m*m;
        mu[ch] = m;
        rstd[ch] = rsqrtf(var + 1e-5f);
    }
}

// ---------------- fused BN+ReLU -> FFT512 -> pointwise -> IFFT512 ----------------
// Forward = DIF (natural in, bit-rev out); pointwise coeffs are frequency-
// independent (diag + scalar bias per channel) so bit-rev order is irrelevant;
// inverse = DIT (bit-rev in, natural out). ortho norm = 1/sqrt(512) each way.
__global__ void fft_kernel(const float* __restrict__ bn1g, const float* __restrict__ bn1b,
                           const float* __restrict__ rmat, const float* __restrict__ imat,
                           const float* __restrict__ rb,   const float* __restrict__ ib) {
    int h = blockIdx.x, b = blockIdx.y;
    int tid = threadIdx.x;                 // 256 threads
    __shared__ float2 buf[512];
    float m  = g_mu1[h];
    float rs = g_rstd1[h] * bn1g[h];
    float bb = bn1b[h];
    #pragma unroll
    for (int n = tid; n < 512; n += 256) {
        float v = (g_g1[(b*512 + n)*256 + h] - m) * rs + bb;
        buf[n] = make_float2(fmaxf(v, 0.f), 0.f);
    }
    __syncthreads();
    // forward DIF
    #pragma unroll
    for (int st = 8; st >= 0; st--) {
        int mh = 1 << st;
        int j  = tid & (mh - 1);
        int i0 = ((tid >> st) << (st + 1)) + j;
        float2 a = buf[i0], c2 = buf[i0 + mh];
        float ang = -3.14159265358979f * (float)j / (float)mh;
        float sw, cw; __sincosf(ang, &sw, &cw);
        float tr = a.x - c2.x, ti = a.y - c2.y;
        buf[i0]      = make_float2(a.x + c2.x, a.y + c2.y);
        buf[i0 + mh] = make_float2(tr*cw - ti*sw, tr*sw + ti*cw);
        __syncthreads();
    }
    const float scl = 0.04419417382415922f;   // 1/sqrt(512)
    float rd  = rmat[h*256 + h];
    float idg = imat[h*256 + h];
    float rbv = rb[h], ibv = ib[h];
    #pragma unroll
    for (int n = tid; n < 512; n += 256) {
        float2 v = buf[n];
        float re = v.x * scl, im = v.y * scl;
        buf[n] = make_float2(fmaxf(re*rd - im*idg + rbv, 0.f),
                             fmaxf(im*rd + re*idg + ibv, 0.f));
    }
    __syncthreads();
    // inverse DIT
    #pragma unroll
    for (int st = 0; st <= 8; st++) {
        int mh = 1 << st;
        int j  = tid & (mh - 1);
        int i0 = ((tid >> st) << (st + 1)) + j;
        float2 a = buf[i0], c2 = buf[i0 + mh];
        float ang = 3.14159265358979f * (float)j / (float)mh;
        float sw, cw; __sincosf(ang, &sw, &cw);
        float tr = c2.x*cw - c2.y*sw, ti = c2.x*sw + c2.y*cw;
        buf[i0]      = make_float2(a.x + tr, a.y + ti);
        buf[i0 + mh] = make_float2(a.x - tr, a.y - ti);
        __syncthreads();
    }
    #pragma unroll
    for (int n = tid; n < 512; n += 256)
        g_h2[(b*512 + n)*256 + h] = buf[n].x * scl;
}

// ---------------- final: out = xo + BN2(g2) ----------------
__global__ void final_out(const float* __restrict__ bn2g, const float* __restrict__ bn2b,
                          float* __restrict__ out) {
    int idx = blockIdx.x*256 + threadIdx.x;    // 2048*128
    int c = idx & 127;
    float v = g_g2[idx];
    out[idx] = g_xo[idx] + (v - g_mu2[c]) * g_rstd2[c] * bn2g[c] + bn2b[c];
}

// ==================================================================================
extern "C" void kernel_launch(void* const* d_in, const int* in_sizes, int n_in,
                              void* d_out, int out_size) {
    const float* x         = (const float*)d_in[0];
    const float* ln_w      = (const float*)d_in[1];
    const float* ln_b      = (const float*)d_in[2];
    const float* in_proj_w = (const float*)d_in[3];
    const float* conv_w    = (const float*)d_in[4];
    const float* conv_b    = (const float*)d_in[5];
    const float* x_proj_w  = (const float*)d_in[6];
    const float* dt_proj_w = (const float*)d_in[7];
    const float* dt_proj_b = (const float*)d_in[8];
    const float* A_log     = (const float*)d_in[9];
    const float* D_param   = (const float*)d_in[10];
    const float* out_proj_w= (const float*)d_in[11];
    const float* norm1_w   = (const float*)d_in[12];
    const float* norm1_b   = (const float*)d_in[13];
    const float* norm2_w   = (const float*)d_in[14];
    const float* norm2_b   = (const float*)d_in[15];
    const float* fc1_w     = (const float*)d_in[16];
    const float* bn1_g     = (const float*)d_in[17];
    const float* bn1_b     = (const float*)d_in[18];
    const float* r_mat     = (const float*)d_in[19];
    const float* i_mat     = (const float*)d_in[20];
    const float* rb        = (const float*)d_in[21];
    const float* ib        = (const float*)d_in[22];
    const float* fc2_w     = (const float*)d_in[23];
    const float* bn2_g     = (const float*)d_in[24];
    const float* bn2_b     = (const float*)d_in[25];
    float* out = (float*)d_out;

    float *p_xn, *p_xz, *p_xh, *p_dbl, *p_y2, *p_xoacc, *p_xn2, *p_g1, *p_h2, *p_g2;
    float *p_mu1, *p_rstd1, *p_mu2, *p_rstd2;
    cudaGetSymbolAddress((void**)&p_xn,    g_xn);
    cudaGetSymbolAddress((void**)&p_xz,    g_xz);
    cudaGetSymbolAddress((void**)&p_xh,    g_xh);
    cudaGetSymbolAddress((void**)&p_dbl,   g_dbl);
    cudaGetSymbolAddress((void**)&p_y2,    g_y2);
    cudaGetSymbolAddress((void**)&p_xoacc, g_xoacc);
    cudaGetSymbolAddress((void**)&p_xn2,   g_xn2);
    cudaGetSymbolAddress((void**)&p_g1,    g_g1);
    cudaGetSymbolAddress((void**)&p_h2,    g_h2);
    cudaGetSymbolAddress((void**)&p_g2,    g_g2);
    cudaGetSymbolAddress((void**)&p_mu1,   g_mu1);
    cudaGetSymbolAddress((void**)&p_rstd1, g_rstd1);
    cudaGetSymbolAddress((void**)&p_mu2,   g_mu2);
    cudaGetSymbolAddress((void**)&p_rstd2, g_rstd2);

    // shared pre-work
    ln128<<<NTOK, 128>>>(x, ln_w, ln_b, p_xn);
    gemm64<true,  false><<<dim3(8, 32), 256>>>(p_xn, in_proj_w, p_xz, NTOK, 512, 128);
    acoef_kernel<<<64, 256>>>(A_log);

    // four chunked mamba runs
    for (int r = 0; r < 4; r++) {
        int lr = 512 >> r;
        conv_silu<<<NTOK, 256>>>(conv_w, conv_b, lr);
        gemm64<true, false><<<dim3(3, 32), 256>>>(p_xh, x_proj_w, p_dbl, NTOK, DBLW, 256);
        dt_kernel<<<NTOK, 256>>>(dt_proj_w, dt_proj_b);
        cm_copy<<<512, 256>>>(out + 262144 + r*131072);
        scan_kernel<<<dim3(2048 / lr, 32), 256>>>(lr);
        y2_kernel<<<NTOK, 256>>>(D_param);
        if (r == 0)
            gemm64<true, false><<<dim3(2, 32), 256>>>(p_y2, out_proj_w, p_xoacc, NTOK, 128, 256);
        else
            gemm64<true, true ><<<dim3(2, 32), 256>>>(p_y2, out_proj_w, p_xoacc, NTOK, 128, 256);
    }

    // residual norms + freq FFN
    norm12<<<NTOK, 128>>>(x, norm1_w, norm1_b, norm2_w, norm2_b);
    gemm64<false, false><<<dim3(4, 32), 256>>>(p_xn2, fc1_w, p_g1, NTOK, 256, 128);
    bn_stats<<<256, 256>>>(p_g1, 256, p_mu1, p_rstd1);
    fft_kernel<<<dim3(256, 4), 256>>>(bn1_g, bn1_b, r_mat, i_mat, rb, ib);
    gemm64<false, false><<<dim3(2, 32), 256>>>(p_h2, fc2_w, p_g2, NTOK, 128, 256);
    bn_stats<<<128, 256>>>(p_g2, 128, p_mu2, p_rstd2);
    final_out<<<1024, 256>>>(bn2_g, bn2_b, out);
}